// round 10
// baseline (speedup 1.0000x reference)
#include <cuda_runtime.h>
#include <cstdint>

#define KTOT   4194304
#define CHUNK  64                      // outputs per chain
#define WARM   128                     // warmup (redundant) steps per chain
#define TS     32                      // steps per tile
#define NT     6                       // tiles per chain
#define WTILES 4                       // warmup tiles
#define NCH    (KTOT / CHUNK)          // 65536 chains
#define NBLK   (NCH / 64)              // 1024 one-warp blocks (64 chains/warp, ILP=2)
#define PITCH  34                      // smem row pitch (floats, 8B-aligned)
#define BROWS  66                      // rows per parity buffer (64 chains + 2 shift)

__device__ __forceinline__ float frcp_ap(float x) {
    float r; asm("rcp.approx.ftz.f32 %0, %1;" : "=f"(r) : "f"(x)); return r;
}
__device__ __forceinline__ float fsqrt_ap(float x) {
    float r; asm("sqrt.approx.f32 %0, %1;" : "=f"(r) : "f"(x)); return r;
}
__device__ __forceinline__ void cp_async8(uint32_t dst, const float* src) {
    asm volatile("cp.async.ca.shared.global [%0], [%1], 8;" :: "r"(dst), "l"(src));
}
#define CP_COMMIT() asm volatile("cp.async.commit_group;" ::: "memory")
#define CP_WAIT1()  asm volatile("cp.async.wait_group 1;"  ::: "memory")
#define CP_WAIT0()  asm volatile("cp.async.wait_group 0;"  ::: "memory")

struct P { float nu, Amu, As, bmu, Bs, wmu, ws; };

__device__ __forceinline__ void gas_step(const float y, float& mu, float& s2, const P& p) {
    // scale*r = (nu+1)*s2*r / (nu*s2 + r^2): one rcp, 10 fma-pipe ops
    const float r_  = y - mu;
    const float rr  = r_ * r_;
    const float d   = fmaf(p.nu, s2, rr);
    const float q   = frcp_ap(d);
    const float s2r = s2 * r_;
    const float mb  = fmaf(p.bmu, mu, p.wmu);   // off critical path
    const float sb  = fmaf(p.Bs,  s2, p.ws);    // off critical path
    const float N   = s2r * q;
    mu = fmaf(p.Amu, N, mb);
    s2 = fmaf(p.As, N * r_, sb);
}

// Prologue-only staging of one parity buffer: rows 0..65, row r = y[base+64r, +32).
// lane -> r0=lane>>4, col=(lane&15)*2; k advances 2 rows (128 floats in y).
template<bool GUARD>
__device__ __forceinline__ void stage_buf(
    const int base, const int lane, const float* __restrict__ y, float* buf)
{
    const int r0  = lane >> 4;
    const int col = (lane & 15) * 2;
    uint32_t dst = (uint32_t)__cvta_generic_to_shared(buf + r0 * PITCH + col);
    const int g0 = base + r0 * 64 + col;
    #pragma unroll
    for (int k = 0; k < 33; ++k) {             // rows 2k+r0 = 0..65
        int g = g0 + k * 128;
        if (GUARD) g = max(g, 0);              // warp 0 rows 0/1: pre-t0, skipped
        cp_async8(dst + (uint32_t)(k * (2 * PITCH * 4)), y + g);
    }
    CP_COMMIT();
}

// TS steps of tile tau for both chains (A = row lane+m, B = row lane+32+m).
// Loads pipelined one pair ahead. EMIT: mu in place (own dead row), s2 -> sg.
template<bool GUARD, bool EMIT>
__device__ __forceinline__ void compute_tile(
    const int tau, const int skipA,
    float* rpA, float* rpB, float* sgA, float* sgB,
    float& muA, float& s2A, float& muB, float& s2B, const P& p)
{
    float2 ca = *reinterpret_cast<const float2*>(rpA);
    float2 cb = *reinterpret_cast<const float2*>(rpB);
    #pragma unroll
    for (int j = 0; j < TS / 2; ++j) {
        float2 na = ca, nb = cb;
        if (j < TS / 2 - 1) {
            na = *reinterpret_cast<const float2*>(rpA + 2 * j + 2);
            nb = *reinterpret_cast<const float2*>(rpB + 2 * j + 2);
        }
        if (GUARD) {
            if (tau * TS + 2 * j     >= skipA) gas_step(ca.x, muA, s2A, p);
            gas_step(cb.x, muB, s2B, p);
            if (tau * TS + 2 * j + 1 >= skipA) gas_step(ca.y, muA, s2A, p);
            gas_step(cb.y, muB, s2B, p);
        } else {
            gas_step(ca.x, muA, s2A, p);
            gas_step(cb.x, muB, s2B, p);
            const float mA0 = muA, vA0 = s2A, mB0 = muB, vB0 = s2B;
            gas_step(ca.y, muA, s2A, p);
            gas_step(cb.y, muB, s2B, p);
            if (EMIT) {
                *reinterpret_cast<float2*>(rpA + 2 * j) = make_float2(mA0, muA);
                *reinterpret_cast<float2*>(rpB + 2 * j) = make_float2(mB0, muB);
                *reinterpret_cast<float2*>(sgA + 2 * j) = make_float2(vA0, s2A);
                *reinterpret_cast<float2*>(sgB + 2 * j) = make_float2(vB0, s2B);
            }
        }
        ca = na; cb = nb;
    }
}

// Coalesced flush of emit tile t: mu at buffer row idx+2, s2 at sg row idx.
__device__ __forceinline__ void flush_tile(
    const int t, const int wcb, const int lane,
    const float* bp, const float* sg, float* __restrict__ out)
{
    const int r0  = lane >> 4;
    const int col = (lane & 15) * 2;
    const int ob  = (t - WTILES) * TS;
    #pragma unroll
    for (int k = 0; k < 32; ++k) {
        const int idx = 2 * k + r0;                 // chain index 0..63
        const float2 m = *reinterpret_cast<const float2*>(
            bp + (idx + 2) * PITCH + col);
        float2 g = *reinterpret_cast<const float2*>(sg + idx * PITCH + col);
        g.x = fsqrt_ap(g.x); g.y = fsqrt_ap(g.y);
        const int gi = (wcb + idx) * CHUNK + ob + col;
        *reinterpret_cast<float2*>(&out[gi])        = m;
        *reinterpret_cast<float2*>(&out[KTOT + gi]) = g;
    }
}

template<bool GUARD>
__device__ __forceinline__ void run_warp(
    const int wcb, const int lane,
    const float* __restrict__ y, float* __restrict__ out,
    float* bufE, float* bufO, float* sg,
    float muA, float s2A, float muB, float s2B, const P& p, const int skipA)
{
    // whole input window staged up front; steady loop has NO global loads
    stage_buf<GUARD>(wcb * CHUNK - WARM,      lane, y, bufE);   // group 0
    stage_buf<GUARD>(wcb * CHUNK - WARM + TS, lane, y, bufO);   // group 1

    float* sgA = sg + lane * PITCH;
    float* sgB = sg + (lane + 32) * PITCH;

    #pragma unroll 1
    for (int t = 0; t < NT; ++t) {
        if (t == 0) CP_WAIT1();
        else if (t == 1) CP_WAIT0();
        __syncwarp();
        float* bp = (t & 1) ? bufO : bufE;
        const int m = t >> 1;
        float* rpA = bp + (lane + m) * PITCH;
        float* rpB = bp + (lane + 32 + m) * PITCH;

        if (t < WTILES) {
            if (GUARD)
                compute_tile<true,  false>(t, skipA, rpA, rpB, sgA, sgB,
                                           muA, s2A, muB, s2B, p);
            else
                compute_tile<false, false>(t, skipA, rpA, rpB, sgA, sgB,
                                           muA, s2A, muB, s2B, p);
        } else {
            compute_tile<false, true>(t, skipA, rpA, rpB, sgA, sgB,
                                      muA, s2A, muB, s2B, p);
            __syncwarp();
            flush_tile(t, wcb, lane, bp, sg, out);
            __syncwarp();   // flush reads done before t=5 reuses sg
        }
    }
}

__global__ __launch_bounds__(32)
void argas_kernel(
    const float* __restrict__ y,
    const float* __restrict__ p_lastmu,  const float* __restrict__ p_lastsig,
    const float* __restrict__ p_amu,     const float* __restrict__ p_as,
    const float* __restrict__ p_bmu,     const float* __restrict__ p_bs,
    const float* __restrict__ p_wmu,     const float* __restrict__ p_ws,
    const float* __restrict__ p_nu,      const float* __restrict__ p_str,
    float* __restrict__ out)
{
    __shared__ float bufE[BROWS][PITCH];   // even-tile rows (row r = chainIdx+m)
    __shared__ float bufO[BROWS][PITCH];   // odd-tile rows
    __shared__ float sg[64][PITCH];        // s2 staging for emit tiles

    const int lane = threadIdx.x;
    const int wcb  = blockIdx.x * 64;      // warp's chain base (64 chains/warp)

    P p;
    const float nu       = *p_nu;
    const float strength = *p_str;
    const float amu  = (*p_amu) * strength;
    const float as_  = (*p_as)  * strength;
    const float bmu  = *p_bmu;
    const float bs   = *p_bs;
    const float nup1 = nu + 1.0f;
    p.nu  = nu;
    p.Amu = bmu * amu * nup1;
    p.As  = bs  * as_ * nup1;
    p.bmu = bmu;
    p.Bs  = bs * (1.0f - as_);
    p.wmu = *p_wmu;
    p.ws  = *p_ws;

    const float mu0 = *p_lastmu;   // chains whose warmup reaches before idx 0
    const float s20 = *p_lastsig;  // skip those steps; they start exact.

    // chain A = wcb+lane, chain B = wcb+32+lane. Only global chains 0,1
    // (warp 0, lanes 0,1, A side) have warmup windows reaching before idx 0.
    const int skipA = WARM - (wcb + lane) * CHUNK;

    if (wcb == 0)
        run_warp<true >(wcb, lane, y, out, &bufE[0][0], &bufO[0][0], &sg[0][0],
                        mu0, s20, mu0, s20, p, skipA);
    else
        run_warp<false>(wcb, lane, y, out, &bufE[0][0], &bufO[0][0], &sg[0][0],
                        mu0, s20, mu0, s20, p, skipA);
}

extern "C" void kernel_launch(void* const* d_in, const int* in_sizes, int n_in,
                              void* d_out, int out_size) {
    const float* y = (const float*)d_in[0];
    argas_kernel<<<NBLK, 32>>>(
        y,
        (const float*)d_in[1],  (const float*)d_in[2],
        (const float*)d_in[3],  (const float*)d_in[4],
        (const float*)d_in[5],  (const float*)d_in[6],
        (const float*)d_in[7],  (const float*)d_in[8],
        (const float*)d_in[9],  (const float*)d_in[10],
        (float*)d_out);
}

// round 11
// speedup vs baseline: 1.1085x; 1.1085x over previous
#include <cuda_runtime.h>
#include <cstdint>

#define KTOT   4194304
#define CHUNK  32                      // outputs per chain
#define WARM   128                     // warmup (redundant) steps per chain
#define TS     32                      // steps per tile (== CHUNK: shift 1 row/tile)
#define NT     5                       // tiles per chain
#define WTILES 4                       // warmup tiles
#define NCH    (KTOT / CHUNK)          // 131072 chains
#define WPB    2                       // warps per block
#define TPB    (WPB * 32)
#define NBLK   (NCH / 32 / WPB)        // 2048 blocks (4096 warps, 1 chain/thread)
#define PITCH  34                      // input-buffer row pitch (floats)
#define BROWS  36                      // rows: 32 chains + 4 tile shifts
#define SGP    18                      // sigma half-buffer row pitch (floats)

__device__ __forceinline__ float frcp_ap(float x) {
    float r; asm("rcp.approx.ftz.f32 %0, %1;" : "=f"(r) : "f"(x)); return r;
}
__device__ __forceinline__ float fsqrt_ap(float x) {
    float r; asm("sqrt.approx.f32 %0, %1;" : "=f"(r) : "f"(x)); return r;
}
__device__ __forceinline__ void cp_async8(uint32_t dst, const float* src) {
    asm volatile("cp.async.ca.shared.global [%0], [%1], 8;" :: "r"(dst), "l"(src));
}
#define CP_COMMIT() asm volatile("cp.async.commit_group;" ::: "memory")
#define CP_WAIT0()  asm volatile("cp.async.wait_group 0;"  ::: "memory")

struct P { float nu, Amu, As, bmu, Bs, wmu, ws; };

__device__ __forceinline__ void gas_step(const float y, float& mu, float& s2, const P& p) {
    // scale*r = (nu+1)*s2*r / (nu*s2 + r^2): one rcp, 10 fma-pipe ops
    const float r_  = y - mu;
    const float rr  = r_ * r_;
    const float d   = fmaf(p.nu, s2, rr);
    const float q   = frcp_ap(d);
    const float s2r = s2 * r_;
    const float mb  = fmaf(p.bmu, mu, p.wmu);   // off critical path
    const float sb  = fmaf(p.Bs,  s2, p.ws);    // off critical path
    const float N   = s2r * q;
    mu = fmaf(p.Amu, N, mb);
    s2 = fmaf(p.As, N * r_, sb);
}

template<bool GUARD>
__device__ __forceinline__ void run_warp(
    const int wcb, const int lane,
    const float* __restrict__ y, float* __restrict__ out,
    float* buf, float* sg, float mu, float s2, const P& p, const int skip)
{
    // ---- prologue: stage the warp's ENTIRE 36-row input window (4.6KB) ----
    {
        const int r0  = lane >> 4;
        const int col = (lane & 15) * 2;
        uint32_t dst = (uint32_t)__cvta_generic_to_shared(buf + r0 * PITCH + col);
        const int g0 = wcb * CHUNK - WARM + r0 * TS + col;
        #pragma unroll
        for (int k = 0; k < 18; ++k) {          // rows 2k+r0 = 0..35
            int g = g0 + k * 64;
            if (GUARD) g = max(g, 0);           // warp0 rows 0..3: pre-t0, skipped
            cp_async8(dst + (uint32_t)(k * (2 * PITCH * 4)), y + g);
        }
        CP_COMMIT();
        CP_WAIT0();
        __syncwarp();
    }

    // ---- warmup tiles 0..3 (no output); steady loop has NO global loads ----
    #pragma unroll 1
    for (int t = 0; t < WTILES; ++t) {
        float* rp = buf + (lane + t) * PITCH;
        float2 cur = *reinterpret_cast<const float2*>(rp);
        #pragma unroll
        for (int j = 0; j < TS / 2; ++j) {
            float2 nxt = cur;
            if (j < TS / 2 - 1)
                nxt = *reinterpret_cast<const float2*>(rp + 2 * j + 2);
            if (GUARD) {
                if (t * TS + 2 * j     >= skip) gas_step(cur.x, mu, s2, p);
                if (t * TS + 2 * j + 1 >= skip) gas_step(cur.y, mu, s2, p);
            } else {
                gas_step(cur.x, mu, s2, p);
                gas_step(cur.y, mu, s2, p);
            }
            cur = nxt;
        }
    }

    // ---- emit tile (t = 4): two 16-step halves, sigma flushed per half ----
    {
        float* rp  = buf + (lane + 4) * PITCH;   // own row; in-place mu is safe
        float* sgr = sg + lane * SGP;
        #pragma unroll 1
        for (int h = 0; h < 2; ++h) {
            float2 cur = *reinterpret_cast<const float2*>(rp + 16 * h);
            #pragma unroll
            for (int j = 0; j < 8; ++j) {
                float2 nxt = cur;
                if (j < 7)
                    nxt = *reinterpret_cast<const float2*>(rp + 16 * h + 2 * j + 2);
                gas_step(cur.x, mu, s2, p);
                const float m0 = mu, v0 = s2;
                gas_step(cur.y, mu, s2, p);
                *reinterpret_cast<float2*>(rp + 16 * h + 2 * j) = make_float2(m0, mu);
                *reinterpret_cast<float2*>(sgr + 2 * j)         = make_float2(v0, s2);
                cur = nxt;
            }
            __syncwarp();
            // flush sigma half h: 32 chains x 16 steps (64B-coalesced)
            {
                const int r0s = lane >> 3;
                const int c   = (lane & 7) * 2;
                #pragma unroll
                for (int k = 0; k < 8; ++k) {
                    const int row = 4 * k + r0s;
                    float2 g = *reinterpret_cast<const float2*>(sg + row * SGP + c);
                    g.x = fsqrt_ap(g.x); g.y = fsqrt_ap(g.y);
                    *reinterpret_cast<float2*>(
                        &out[KTOT + (wcb + row) * CHUNK + 16 * h + c]) = g;
                }
            }
            __syncwarp();
        }
        // flush mu: full 32 steps from buf rows (chain i at buffer row i+4)
        {
            const int r0  = lane >> 4;
            const int col = (lane & 15) * 2;
            #pragma unroll
            for (int k = 0; k < 16; ++k) {
                const int row = 2 * k + r0;
                const float2 m = *reinterpret_cast<const float2*>(
                    buf + (row + 4) * PITCH + col);
                *reinterpret_cast<float2*>(&out[(wcb + row) * CHUNK + col]) = m;
            }
        }
    }
}

__global__ __launch_bounds__(TPB, 14)
void argas_kernel(
    const float* __restrict__ y,
    const float* __restrict__ p_lastmu,  const float* __restrict__ p_lastsig,
    const float* __restrict__ p_amu,     const float* __restrict__ p_as,
    const float* __restrict__ p_bmu,     const float* __restrict__ p_bs,
    const float* __restrict__ p_wmu,     const float* __restrict__ p_ws,
    const float* __restrict__ p_nu,      const float* __restrict__ p_str,
    float* __restrict__ out)
{
    __shared__ float buf[WPB][BROWS][PITCH];   // per-warp single input buffer
    __shared__ float sg[WPB][32][SGP];         // per-warp sigma half-buffer

    const int warp  = threadIdx.x >> 5;
    const int lane  = threadIdx.x & 31;
    const int wcb   = (blockIdx.x * WPB + warp) * 32;   // warp's chain base
    const int chain = wcb + lane;

    P p;
    const float nu       = *p_nu;
    const float strength = *p_str;
    const float amu  = (*p_amu) * strength;
    const float as_  = (*p_as)  * strength;
    const float bmu  = *p_bmu;
    const float bs   = *p_bs;
    const float nup1 = nu + 1.0f;
    p.nu  = nu;
    p.Amu = bmu * amu * nup1;
    p.As  = bs  * as_ * nup1;
    p.bmu = bmu;
    p.Bs  = bs * (1.0f - as_);
    p.wmu = *p_wmu;
    p.ws  = *p_ws;

    const float mu0 = *p_lastmu;   // chains whose warmup reaches before idx 0
    const float s20 = *p_lastsig;  // skip those steps; they start exact.

    const int skip = WARM - chain * CHUNK;   // >0 only for chains 0..3 (warp 0)

    if (wcb == 0)
        run_warp<true >(wcb, lane, y, out, &buf[warp][0][0], &sg[warp][0][0],
                        mu0, s20, p, skip);
    else
        run_warp<false>(wcb, lane, y, out, &buf[warp][0][0], &sg[warp][0][0],
                        mu0, s20, p, skip);
}

extern "C" void kernel_launch(void* const* d_in, const int* in_sizes, int n_in,
                              void* d_out, int out_size) {
    const float* y = (const float*)d_in[0];
    argas_kernel<<<NBLK, TPB>>>(
        y,
        (const float*)d_in[1],  (const float*)d_in[2],
        (const float*)d_in[3],  (const float*)d_in[4],
        (const float*)d_in[5],  (const float*)d_in[6],
        (const float*)d_in[7],  (const float*)d_in[8],
        (const float*)d_in[9],  (const float*)d_in[10],
        (float*)d_out);
}

// round 12
// speedup vs baseline: 1.2224x; 1.1028x over previous
#include <cuda_runtime.h>
#include <cstdint>

#define KTOT   4194304
#define CHUNK  64                      // outputs per chain
#define WARM   128                     // warmup (redundant) steps per chain
#define TS     32                      // steps per tile
#define NT     6                       // tiles per chain
#define WTILES 4                       // warmup tiles
#define NCH    (KTOT / CHUNK)          // 65536 chains (1 per thread)
#define WPB    2                       // warps per block
#define TPB    (WPB * 32)
#define NBLK   (NCH / 32 / WPB)        // 1024 blocks (2048 warps)
#define PITCH  34                      // buffer row pitch in floats
#define BROWS  34                      // rows per parity buffer (32 + 2 shift)
#define SGP    18                      // sigma half-buffer pitch (16 steps + pad)

__device__ __forceinline__ float frcp_ap(float x) {
    float r; asm("rcp.approx.ftz.f32 %0, %1;" : "=f"(r) : "f"(x)); return r;
}
__device__ __forceinline__ float fsqrt_ap(float x) {
    float r; asm("sqrt.approx.f32 %0, %1;" : "=f"(r) : "f"(x)); return r;
}
__device__ __forceinline__ void cp_async8(uint32_t dst, const float* src) {
    asm volatile("cp.async.ca.shared.global [%0], [%1], 8;" :: "r"(dst), "l"(src));
}
#define CP_COMMIT() asm volatile("cp.async.commit_group;" ::: "memory")
#define CP_WAIT1()  asm volatile("cp.async.wait_group 1;"  ::: "memory")
#define CP_WAIT0()  asm volatile("cp.async.wait_group 0;"  ::: "memory")

struct P { float nu, Amu, As, bmu, Bs, wmu, ws; };

__device__ __forceinline__ void gas_step(const float y, float& mu, float& s2, const P& p) {
    // scale*r = (nu+1)*s2*r / (nu*s2 + r^2): one rcp, 10 fma-pipe ops
    const float r_  = y - mu;
    const float rr  = r_ * r_;
    const float d   = fmaf(p.nu, s2, rr);
    const float q   = frcp_ap(d);
    const float s2r = s2 * r_;
    const float mb  = fmaf(p.bmu, mu, p.wmu);   // off critical path
    const float sb  = fmaf(p.Bs,  s2, p.ws);    // off critical path
    const float N   = s2r * q;
    mu = fmaf(p.Amu, N, mb);
    s2 = fmaf(p.As, N * r_, sb);
}

// Stage rows 0..31 of a parity buffer. Row r holds y[base + 64r, +32).
template<bool GUARD>
__device__ __forceinline__ void stage_init(
    const int base, const int lane, const float* __restrict__ y, float* buf)
{
    const int r0  = lane >> 4;
    const int col = (lane & 15) * 2;
    uint32_t dst = (uint32_t)__cvta_generic_to_shared(buf + r0 * PITCH + col);
    const int g0 = base + r0 * 64 + col;
    #pragma unroll
    for (int k = 0; k < 16; ++k) {               // rows 2k+r0 = 0..31
        int g = g0 + k * 128;
        if (GUARD) g = max(g, 0);                // warp0 pre-t0 slots: skipped
        cp_async8(dst + (uint32_t)(k * (2 * PITCH * 4)), y + g);
    }
    CP_COMMIT();
}

// Stage one extension row (32 floats) of a parity buffer; all lanes commit.
__device__ __forceinline__ void stage_row(
    const int row, const int base, const int lane,
    const float* __restrict__ y, float* buf)
{
    if (lane < 16) {
        uint32_t dst = (uint32_t)__cvta_generic_to_shared(buf + row * PITCH + lane * 2);
        cp_async8(dst, y + base + 64 * row + lane * 2);   // always >= 0 here
    }
    CP_COMMIT();
}

// 16 steps (half tile) from a REGISTER preload — no smem access inside the
// arithmetic window. EMIT: mu written back in place (own dead row), s2 -> sgr.
template<bool GUARD, bool EMIT>
__device__ __forceinline__ void do_half(
    const int t, const int h, const int skip,
    float* rp, float* sgr, float& mu, float& s2, const P& p)
{
    float2 v[8];
    #pragma unroll
    for (int i = 0; i < 8; ++i)                  // 8-deep LDS.64 burst (MLP)
        v[i] = *reinterpret_cast<const float2*>(rp + 16 * h + 2 * i);
    #pragma unroll
    for (int i = 0; i < 8; ++i) {
        if (GUARD) {
            if (t * TS + 16 * h + 2 * i     >= skip) gas_step(v[i].x, mu, s2, p);
            if (t * TS + 16 * h + 2 * i + 1 >= skip) gas_step(v[i].y, mu, s2, p);
        } else {
            gas_step(v[i].x, mu, s2, p);
            const float m0 = mu, v0 = s2;
            gas_step(v[i].y, mu, s2, p);
            if (EMIT) {
                *reinterpret_cast<float2*>(rp + 16 * h + 2 * i) = make_float2(m0, mu);
                *reinterpret_cast<float2*>(sgr + 2 * i)         = make_float2(v0, s2);
            }
        }
    }
}

// Flush one sigma half: 32 chains x 16 steps, sqrt applied here.
__device__ __forceinline__ void flush_sigma_half(
    const int t, const int h, const int wcb, const int lane,
    const float* sg, float* __restrict__ out)
{
    const int r0 = lane >> 3;
    const int c  = (lane & 7) * 2;
    const int ob = (t - WTILES) * TS + 16 * h;
    #pragma unroll
    for (int k = 0; k < 8; ++k) {
        const int row = 4 * k + r0;
        float2 g = *reinterpret_cast<const float2*>(sg + row * SGP + c);
        g.x = fsqrt_ap(g.x); g.y = fsqrt_ap(g.y);
        *reinterpret_cast<float2*>(&out[KTOT + (wcb + row) * CHUNK + ob + c]) = g;
    }
}

// Flush mu for a whole emit tile: chain i's data sits at buffer row i+ro.
__device__ __forceinline__ void flush_mu(
    const int t, const int ro, const int wcb, const int lane,
    const float* bp, float* __restrict__ out)
{
    const int r0  = lane >> 4;
    const int col = (lane & 15) * 2;
    const int ob  = (t - WTILES) * TS;
    #pragma unroll
    for (int k = 0; k < 16; ++k) {
        const int row = 2 * k + r0;
        const float2 m = *reinterpret_cast<const float2*>(
            bp + (row + ro) * PITCH + col);
        *reinterpret_cast<float2*>(&out[(wcb + row) * CHUNK + ob + col]) = m;
    }
}

template<bool GUARD>
__device__ __forceinline__ void run_warp(
    const int wcb, const int lane,
    const float* __restrict__ y, float* __restrict__ out,
    float* bufE, float* bufO, float* sg,
    float mu, float s2, const P& p, const int skip)
{
    const int baseE = wcb * CHUNK - WARM;        // row r of E = y[baseE+64r,+32)
    const int baseO = baseE + 32;                // row r of O = y[baseO+64r,+32)

    stage_init<GUARD>(baseE, lane, y, bufE);     // group 0
    stage_init<GUARD>(baseO, lane, y, bufO);     // group 1

    float* sgr = sg + lane * SGP;

    #pragma unroll 1
    for (int t = 0; t < NT; ++t) {
        if (t < NT - 1) CP_WAIT1(); else CP_WAIT0();
        __syncwarp();
        float* bp = (t & 1) ? bufO : bufE;
        const int ro = t >> 1;
        float* rp = bp + (lane + ro) * PITCH;

        // stage extension row for tile t+2 (same parity): rows 32,32,33,33
        if (t + 2 < NT)
            stage_row(31 + ((t + 2) >> 1), (t & 1) ? baseO : baseE, lane, y, bp);

        if (t < WTILES) {
            if (GUARD) {
                do_half<true,  false>(t, 0, skip, rp, sgr, mu, s2, p);
                do_half<true,  false>(t, 1, skip, rp, sgr, mu, s2, p);
            } else {
                do_half<false, false>(t, 0, skip, rp, sgr, mu, s2, p);
                do_half<false, false>(t, 1, skip, rp, sgr, mu, s2, p);
            }
        } else {
            #pragma unroll
            for (int h = 0; h < 2; ++h) {
                do_half<false, true>(t, h, skip, rp, sgr, mu, s2, p);
                __syncwarp();
                flush_sigma_half(t, h, wcb, lane, sg, out);
                __syncwarp();                    // sg reads done before reuse
            }
            flush_mu(t, ro, wcb, lane, bp, out);
        }
    }
}

__global__ __launch_bounds__(TPB)
void argas_kernel(
    const float* __restrict__ y,
    const float* __restrict__ p_lastmu,  const float* __restrict__ p_lastsig,
    const float* __restrict__ p_amu,     const float* __restrict__ p_as,
    const float* __restrict__ p_bmu,     const float* __restrict__ p_bs,
    const float* __restrict__ p_wmu,     const float* __restrict__ p_ws,
    const float* __restrict__ p_nu,      const float* __restrict__ p_str,
    float* __restrict__ out)
{
    __shared__ float bufE[WPB][BROWS][PITCH];   // per-warp even-parity rows
    __shared__ float bufO[WPB][BROWS][PITCH];   // per-warp odd-parity rows
    __shared__ float sg[WPB][32][SGP];          // per-warp sigma half-buffer

    const int warp  = threadIdx.x >> 5;
    const int lane  = threadIdx.x & 31;
    const int wcb   = (blockIdx.x * WPB + warp) * 32;   // warp's chain base
    const int chain = wcb + lane;

    P p;
    const float nu       = *p_nu;
    const float strength = *p_str;
    const float amu  = (*p_amu) * strength;
    const float as_  = (*p_as)  * strength;
    const float bmu  = *p_bmu;
    const float bs   = *p_bs;
    const float nup1 = nu + 1.0f;
    p.nu  = nu;
    p.Amu = bmu * amu * nup1;
    p.As  = bs  * as_ * nup1;
    p.bmu = bmu;
    p.Bs  = bs * (1.0f - as_);
    p.wmu = *p_wmu;
    p.ws  = *p_ws;

    const float mu0 = *p_lastmu;   // chains whose warmup reaches before idx 0
    const float s20 = *p_lastsig;  // skip those steps; they start exact.

    const int skip = WARM - chain * CHUNK;   // >0 only for chains 0,1 (warp 0)

    if (wcb == 0)
        run_warp<true >(wcb, lane, y, out,
                        &bufE[warp][0][0], &bufO[warp][0][0], &sg[warp][0][0],
                        mu0, s20, p, skip);
    else
        run_warp<false>(wcb, lane, y, out,
                        &bufE[warp][0][0], &bufO[warp][0][0], &sg[warp][0][0],
                        mu0, s20, p, skip);
}

extern "C" void kernel_launch(void* const* d_in, const int* in_sizes, int n_in,
                              void* d_out, int out_size) {
    const float* y = (const float*)d_in[0];
    argas_kernel<<<NBLK, TPB>>>(
        y,
        (const float*)d_in[1],  (const float*)d_in[2],
        (const float*)d_in[3],  (const float*)d_in[4],
        (const float*)d_in[5],  (const float*)d_in[6],
        (const float*)d_in[7],  (const float*)d_in[8],
        (const float*)d_in[9],  (const float*)d_in[10],
        (float*)d_out);
}

// round 13
// speedup vs baseline: 1.2724x; 1.0409x over previous
#include <cuda_runtime.h>
#include <cstdint>

#define KTOT   4194304
#define CHUNK  64                      // outputs per chain
#define WARM   128                     // warmup window (tile alignment)
#define SKIP0  16                      // steps of tile 0 skipped -> eff. warmup 112
#define TS     32                      // steps per tile
#define NT     6                       // tiles per chain
#define WTILES 4                       // warmup tiles
#define NCH    (KTOT / CHUNK)          // 65536 chains (1 per thread)
#define WPB    2                       // warps per block
#define TPB    (WPB * 32)
#define NBLK   (NCH / 32 / WPB)        // 1024 blocks (2048 warps)
#define PITCH  34                      // buffer row pitch in floats
#define BROWS  34                      // rows per parity buffer (32 + 2 shift)
#define SGP    18                      // sigma half-buffer pitch (16 steps + pad)

__device__ __forceinline__ float frcp_ap(float x) {
    float r; asm("rcp.approx.ftz.f32 %0, %1;" : "=f"(r) : "f"(x)); return r;
}
__device__ __forceinline__ float fsqrt_ap(float x) {
    float r; asm("sqrt.approx.f32 %0, %1;" : "=f"(r) : "f"(x)); return r;
}
__device__ __forceinline__ void cp_async8(uint32_t dst, const float* src) {
    asm volatile("cp.async.ca.shared.global [%0], [%1], 8;" :: "r"(dst), "l"(src));
}
#define CP_COMMIT() asm volatile("cp.async.commit_group;" ::: "memory")
#define CP_WAIT1()  asm volatile("cp.async.wait_group 1;"  ::: "memory")
#define CP_WAIT0()  asm volatile("cp.async.wait_group 0;"  ::: "memory")

struct P { float nu, Amu, As, bmu, Bs, wmu, ws; };

__device__ __forceinline__ void gas_step(const float y, float& mu, float& s2, const P& p) {
    // scale*r = (nu+1)*s2*r/(nu*s2+r^2). Dual-product form: both mu' and s2'
    // are a single fma after q -> critical chain ~40 cyc.
    const float r_   = y - mu;
    const float rr   = r_ * r_;
    const float d    = fmaf(p.nu, s2, rr);
    const float q    = frcp_ap(d);
    const float s2r  = s2 * r_;                  // parallel with d/q
    const float s2rr = s2 * rr;                  // parallel with d/q
    const float mb   = fmaf(p.bmu, mu, p.wmu);   // off critical path
    const float sb   = fmaf(p.Bs,  s2, p.ws);    // off critical path
    mu = fmaf(p.Amu, s2r  * q, mb);
    s2 = fmaf(p.As,  s2rr * q, sb);
}

// Stage rows 0..31 of a parity buffer. Row r holds y[base + 64r, +32).
template<bool GUARD>
__device__ __forceinline__ void stage_init(
    const int base, const int lane, const float* __restrict__ y, float* buf)
{
    const int r0  = lane >> 4;
    const int col = (lane & 15) * 2;
    uint32_t dst = (uint32_t)__cvta_generic_to_shared(buf + r0 * PITCH + col);
    const int g0 = base + r0 * 64 + col;
    #pragma unroll
    for (int k = 0; k < 16; ++k) {               // rows 2k+r0 = 0..31
        int g = g0 + k * 128;
        if (GUARD) g = max(g, 0);                // warp0 pre-t0 slots: skipped
        cp_async8(dst + (uint32_t)(k * (2 * PITCH * 4)), y + g);
    }
    CP_COMMIT();
}

// Stage one extension row (32 floats) of a parity buffer; all lanes commit.
__device__ __forceinline__ void stage_row(
    const int row, const int base, const int lane,
    const float* __restrict__ y, float* buf)
{
    if (lane < 16) {
        uint32_t dst = (uint32_t)__cvta_generic_to_shared(buf + row * PITCH + lane * 2);
        cp_async8(dst, y + base + 64 * row + lane * 2);   // always >= 0 here
    }
    CP_COMMIT();
}

// 16 steps (half tile) from a register preload. EMIT: mu in place, s2 -> sgr.
template<bool GUARD, bool EMIT>
__device__ __forceinline__ void do_half(
    const int t, const int h, const int skip,
    float* rp, float* sgr, float& mu, float& s2, const P& p)
{
    float2 v[8];
    #pragma unroll
    for (int i = 0; i < 8; ++i)                  // 8-deep LDS.64 burst (MLP)
        v[i] = *reinterpret_cast<const float2*>(rp + 16 * h + 2 * i);
    #pragma unroll
    for (int i = 0; i < 8; ++i) {
        if (GUARD) {
            if (t * TS + 16 * h + 2 * i     >= skip) gas_step(v[i].x, mu, s2, p);
            if (t * TS + 16 * h + 2 * i + 1 >= skip) gas_step(v[i].y, mu, s2, p);
        } else {
            gas_step(v[i].x, mu, s2, p);
            const float m0 = mu, v0 = s2;
            gas_step(v[i].y, mu, s2, p);
            if (EMIT) {
                *reinterpret_cast<float2*>(rp + 16 * h + 2 * i) = make_float2(m0, mu);
                *reinterpret_cast<float2*>(sgr + 2 * i)         = make_float2(v0, s2);
            }
        }
    }
}

// Flush one sigma half: 32 chains x 16 steps, sqrt applied here.
__device__ __forceinline__ void flush_sigma_half(
    const int t, const int h, const int wcb, const int lane,
    const float* sg, float* __restrict__ out)
{
    const int r0 = lane >> 3;
    const int c  = (lane & 7) * 2;
    const int ob = (t - WTILES) * TS + 16 * h;
    #pragma unroll
    for (int k = 0; k < 8; ++k) {
        const int row = 4 * k + r0;
        float2 g = *reinterpret_cast<const float2*>(sg + row * SGP + c);
        g.x = fsqrt_ap(g.x); g.y = fsqrt_ap(g.y);
        *reinterpret_cast<float2*>(&out[KTOT + (wcb + row) * CHUNK + ob + c]) = g;
    }
}

// Flush mu for a whole emit tile: chain i's data sits at buffer row i+ro.
__device__ __forceinline__ void flush_mu(
    const int t, const int ro, const int wcb, const int lane,
    const float* bp, float* __restrict__ out)
{
    const int r0  = lane >> 4;
    const int col = (lane & 15) * 2;
    const int ob  = (t - WTILES) * TS;
    #pragma unroll
    for (int k = 0; k < 16; ++k) {
        const int row = 2 * k + r0;
        const float2 m = *reinterpret_cast<const float2*>(
            bp + (row + ro) * PITCH + col);
        *reinterpret_cast<float2*>(&out[(wcb + row) * CHUNK + ob + col]) = m;
    }
}

template<bool GUARD>
__device__ __forceinline__ void run_warp(
    const int wcb, const int lane,
    const float* __restrict__ y, float* __restrict__ out,
    float* bufE, float* bufO, float* sg,
    float mu, float s2, const P& p, const int skip)
{
    const int baseE = wcb * CHUNK - WARM;        // row r of E = y[baseE+64r,+32)
    const int baseO = baseE + 32;                // row r of O = y[baseO+64r,+32)

    stage_init<GUARD>(baseE, lane, y, bufE);     // group 0
    stage_init<GUARD>(baseO, lane, y, bufO);     // group 1

    float* sgr = sg + lane * SGP;

    #pragma unroll 1
    for (int t = 0; t < NT; ++t) {
        if (t < NT - 1) CP_WAIT1(); else CP_WAIT0();
        __syncwarp();
        float* bp = (t & 1) ? bufO : bufE;
        const int ro = t >> 1;
        float* rp = bp + (lane + ro) * PITCH;

        // stage extension row for tile t+2 (same parity): rows 32,32,33,33
        if (t + 2 < NT)
            stage_row(31 + ((t + 2) >> 1), (t & 1) ? baseO : baseE, lane, y, bp);

        if (t < WTILES) {
            if (GUARD) {
                if (t > 0) do_half<true, false>(t, 0, skip, rp, sgr, mu, s2, p);
                do_half<true,  false>(t, 1, skip, rp, sgr, mu, s2, p);
            } else {
                // tile 0: skip first half -> effective warmup = 112 steps
                if (t > 0) do_half<false, false>(t, 0, skip, rp, sgr, mu, s2, p);
                do_half<false, false>(t, 1, skip, rp, sgr, mu, s2, p);
            }
        } else {
            #pragma unroll
            for (int h = 0; h < 2; ++h) {
                do_half<false, true>(t, h, skip, rp, sgr, mu, s2, p);
                __syncwarp();
                flush_sigma_half(t, h, wcb, lane, sg, out);
                __syncwarp();                    // sg reads done before reuse
            }
            flush_mu(t, ro, wcb, lane, bp, out);
        }
    }
}

__global__ __launch_bounds__(TPB)
void argas_kernel(
    const float* __restrict__ y,
    const float* __restrict__ p_lastmu,  const float* __restrict__ p_lastsig,
    const float* __restrict__ p_amu,     const float* __restrict__ p_as,
    const float* __restrict__ p_bmu,     const float* __restrict__ p_bs,
    const float* __restrict__ p_wmu,     const float* __restrict__ p_ws,
    const float* __restrict__ p_nu,      const float* __restrict__ p_str,
    float* __restrict__ out)
{
    __shared__ float bufE[WPB][BROWS][PITCH];   // per-warp even-parity rows
    __shared__ float bufO[WPB][BROWS][PITCH];   // per-warp odd-parity rows
    __shared__ float sg[WPB][32][SGP];          // per-warp sigma half-buffer

    const int warp  = threadIdx.x >> 5;
    const int lane  = threadIdx.x & 31;
    const int wcb   = (blockIdx.x * WPB + warp) * 32;   // warp's chain base
    const int chain = wcb + lane;

    P p;
    const float nu       = *p_nu;
    const float strength = *p_str;
    const float amu  = (*p_amu) * strength;
    const float as_  = (*p_as)  * strength;
    const float bmu  = *p_bmu;
    const float bs   = *p_bs;
    const float nup1 = nu + 1.0f;
    p.nu  = nu;
    p.Amu = bmu * amu * nup1;
    p.As  = bs  * as_ * nup1;
    p.bmu = bmu;
    p.Bs  = bs * (1.0f - as_);
    p.wmu = *p_wmu;
    p.ws  = *p_ws;

    const float mu0 = *p_lastmu;   // chains whose warmup reaches before idx 0
    const float s20 = *p_lastsig;  // skip those steps; they start exact.

    const int skip = WARM - chain * CHUNK;   // >0 only for chains 0,1 (warp 0)

    if (wcb == 0)
        run_warp<true >(wcb, lane, y, out,
                        &bufE[warp][0][0], &bufO[warp][0][0], &sg[warp][0][0],
                        mu0, s20, p, skip);
    else
        run_warp<false>(wcb, lane, y, out,
                        &bufE[warp][0][0], &bufO[warp][0][0], &sg[warp][0][0],
                        mu0, s20, p, skip);
}

extern "C" void kernel_launch(void* const* d_in, const int* in_sizes, int n_in,
                              void* d_out, int out_size) {
    const float* y = (const float*)d_in[0];
    argas_kernel<<<NBLK, TPB>>>(
        y,
        (const float*)d_in[1],  (const float*)d_in[2],
        (const float*)d_in[3],  (const float*)d_in[4],
        (const float*)d_in[5],  (const float*)d_in[6],
        (const float*)d_in[7],  (const float*)d_in[8],
        (const float*)d_in[9],  (const float*)d_in[10],
        (float*)d_out);
}